// round 15
// baseline (speedup 1.0000x reference)
#include <cuda_runtime.h>
#include <cuda_bf16.h>
#include <cstdint>
#include <cstddef>

// Problem constants
#define BATCH 32
#define SEQ   1024
#define VDIM  128
#define EMB   768
#define H1    300
#define DDIM  200
#define MTOT  (BATCH*SEQ)   // 32768
#define HM    (MTOT/2)      // 16384 (per pipeline half)
#define HB    (BATCH/2)     // 16 batches per half

// padded dims
#define HP    320
#define QP    208
#define MEMP  224
#define W1NP  320
#define W2NP  256
#define MATNP 256

typedef __nv_bfloat16 bf16;

// ---------------- helpers ----------------
__device__ __forceinline__ uint32_t pack_bf16(bf16 lo16, bf16 hi16) {
    __nv_bfloat162 t(lo16, hi16);
    return *(uint32_t*)&t;
}
__device__ __forceinline__ void split_bf16(float v, bf16& h, bf16& l) {
    h = __float2bfloat16(v);
    l = __float2bfloat16(v - __bfloat162float(h));
}
__device__ __forceinline__ void split_pack2(float x, float y, uint32_t& hi, uint32_t& lo) {
    bf16 hx, lx, hy, ly;
    split_bf16(x, hx, lx);
    split_bf16(y, hy, ly);
    hi = pack_bf16(hx, hy);
    lo = pack_bf16(lx, ly);
}
__device__ __forceinline__ void mma16816(float* d, const uint32_t* a, const uint32_t* b) {
    asm volatile(
        "mma.sync.aligned.m16n8k16.row.col.f32.bf16.bf16.f32 "
        "{%0,%1,%2,%3}, {%4,%5,%6,%7}, {%8,%9}, {%0,%1,%2,%3};"
        : "+f"(d[0]), "+f"(d[1]), "+f"(d[2]), "+f"(d[3])
        : "r"(a[0]), "r"(a[1]), "r"(a[2]), "r"(a[3]), "r"(b[0]), "r"(b[1]));
}
__device__ __forceinline__ void mma2(float* d, const uint32_t* a, uint32_t b0, uint32_t b1) {
    asm volatile(
        "mma.sync.aligned.m16n8k16.row.col.f32.bf16.bf16.f32 "
        "{%0,%1,%2,%3}, {%4,%5,%6,%7}, {%8,%9}, {%0,%1,%2,%3};"
        : "+f"(d[0]), "+f"(d[1]), "+f"(d[2]), "+f"(d[3])
        : "r"(a[0]), "r"(a[1]), "r"(a[2]), "r"(a[3]), "r"(b0), "r"(b1));
}
__device__ __forceinline__ uint32_t smem_u32(const void* p) {
    uint32_t a;
    asm("{ .reg .u64 t; cvta.to.shared.u64 t, %1; cvt.u32.u64 %0, t; }"
        : "=r"(a) : "l"(p));
    return a;
}
__device__ __forceinline__ void ldmx4(uint32_t* r, uint32_t addr) {
    asm volatile("ldmatrix.sync.aligned.m8n8.x4.shared.b16 {%0,%1,%2,%3}, [%4];"
        : "=r"(r[0]), "=r"(r[1]), "=r"(r[2]), "=r"(r[3]) : "r"(addr));
}
__device__ __forceinline__ void ldmx4t(uint32_t* r, uint32_t addr) {
    asm volatile("ldmatrix.sync.aligned.m8n8.x4.trans.shared.b16 {%0,%1,%2,%3}, [%4];"
        : "=r"(r[0]), "=r"(r[1]), "=r"(r[2]), "=r"(r[3]) : "r"(addr));
}
__device__ __forceinline__ void cpa16(uint32_t dst, const void* src) {
    asm volatile("cp.async.cg.shared.global [%0], [%1], 16;" :: "r"(dst), "l"(src));
}
#define CP_COMMIT() asm volatile("cp.async.commit_group;" ::: "memory")
#define CP_WAIT(n)  asm volatile("cp.async.wait_group %0;" :: "n"(n) : "memory")

// ---------------- static scratch (bf16 hi/lo pairs) ----------------
__device__ __align__(128) bf16 g_embh[(size_t)MTOT * EMB],  g_embl[(size_t)MTOT * EMB];
__device__ __align__(128) bf16 g_memh[(size_t)MTOT * MEMP], g_meml[(size_t)MTOT * MEMP];
__device__ __align__(128) bf16 g_srlh[(size_t)MTOT * VDIM], g_srll[(size_t)MTOT * VDIM];
__device__ __align__(128) bf16 g_hh[(size_t)MTOT * HP],     g_hl[(size_t)MTOT * HP];
__device__ __align__(128) bf16 g_qh[(size_t)MTOT * QP],     g_ql[(size_t)MTOT * QP];
__device__ __align__(128) bf16 g_yh[(size_t)MTOT * QP],     g_yl[(size_t)MTOT * QP];
__device__ __align__(128) bf16 g_ath[(size_t)MTOT * VDIM],  g_atl[(size_t)MTOT * VDIM];
__device__ __align__(128) bf16 g_w1th[W1NP * EMB],  g_w1tl[W1NP * EMB];
__device__ __align__(128) bf16 g_w2th[W2NP * HP],   g_w2tl[W2NP * HP];
__device__ __align__(128) bf16 g_math[MATNP * MEMP], g_matl[MATNP * MEMP];
__device__ __align__(128) bf16 g_wph[VDIM * VDIM],  g_wpl[VDIM * VDIM];
__device__ __align__(128) float g_b1p[HP];
__device__ __align__(128) float g_b2p[QP];

// ---------------- prep kernels ----------------
__global__ void split_pad2(const float* __restrict__ in, bf16* __restrict__ oh,
                           bf16* __restrict__ ol, long long n2, int C, int CP)
{
    long long i2 = (long long)blockIdx.x * blockDim.x + threadIdx.x;
    if (i2 >= n2) return;
    int cp2 = CP >> 1;
    long long r = i2 / cp2;
    int c2 = (int)(i2 - r * cp2) * 2;
    float x = 0.f, y = 0.f;
    if (c2 + 1 < C) {
        float2 v = *(const float2*)(in + r * C + c2);
        x = v.x; y = v.y;
    } else if (c2 < C) {
        x = in[r * C + c2];
    }
    uint32_t h, l;
    split_pack2(x, y, h, l);
    ((uint32_t*)oh)[(r * CP + c2) >> 1] = h;
    ((uint32_t*)ol)[(r * CP + c2) >> 1] = l;
}

__global__ void tsplit(const float* __restrict__ in, bf16* __restrict__ oh,
                       bf16* __restrict__ ol, int K, int N, int KP, int NP)
{
    int i = blockIdx.x * blockDim.x + threadIdx.x;
    if (i >= NP * KP) return;
    int n = i / KP, k = i - n * KP;
    float v = (n < N && k < K) ? in[(size_t)k * N + n] : 0.f;
    bf16 h, l;
    split_bf16(v, h, l);
    oh[i] = h; ol[i] = l;
}

#define WP_A (W1NP * EMB)
#define WP_B (WP_A + W2NP * HP)
#define WP_C (WP_B + HP)
#define WP_D (WP_C + QP)
__global__ void prep_w12(
    const float* __restrict__ W1, const float* __restrict__ W2,
    const float* __restrict__ b1, const float* __restrict__ b2,
    bf16* __restrict__ w1th, bf16* __restrict__ w1tl,
    bf16* __restrict__ w2th, bf16* __restrict__ w2tl,
    float* __restrict__ b1p, float* __restrict__ b2p)
{
    int i = blockIdx.x * blockDim.x + threadIdx.x;
    if (i < WP_A) {
        int n = i / EMB, k = i - n * EMB;
        float v = (n < H1) ? W1[(size_t)k * H1 + n] : 0.f;
        bf16 h, l; split_bf16(v, h, l);
        w1th[i] = h; w1tl[i] = l;
    } else if (i < WP_B) {
        int j = i - WP_A;
        int n = j / HP, k = j - n * HP;
        float v = (n < DDIM && k < H1) ? W2[(size_t)k * DDIM + n] : 0.f;
        bf16 h, l; split_bf16(v, h, l);
        w2th[j] = h; w2tl[j] = l;
    } else if (i < WP_C) {
        int j = i - WP_B;
        b1p[j] = (j < H1) ? b1[j] : 0.f;
    } else if (i < WP_D) {
        int j = i - WP_C;
        b2p[j] = (j < DDIM) ? b2[j] : 0.f;
    }
}

// =====================================================================
// bf16 pre-split GEMM, templated on NF (unchanged — frozen)
// =====================================================================
#define GSTRIDE_W 20

template<int NF, bool RELU, bool SPLITOUT>
__global__ __launch_bounds__(256) void gemm_bf16(
    const bf16* __restrict__ Ah, const bf16* __restrict__ Al,
    const bf16* __restrict__ Bh, const bf16* __restrict__ Bl,
    const float* __restrict__ bias,
    float* __restrict__ C, bf16* __restrict__ Ch, bf16* __restrict__ Cl,
    int Ns, int K)
{
    constexpr int BROWS   = 32 * NF;
    constexpr int STAGE_W = 5120 + 2 * BROWS * GSTRIDE_W;
    constexpr int OFF_AL  = 2560;
    constexpr int OFF_BH  = 5120;
    constexpr int OFF_BL  = 5120 + BROWS * GSTRIDE_W;

    extern __shared__ uint32_t smw[];
    const uint32_t base_b = smem_u32(smw);

    const int tid  = threadIdx.x;
    const int wid  = tid >> 5;
    const int lane = tid & 31;
    const int g    = lane >> 2;
    const int c    = lane & 3;
    const int wm   = wid & 1;
    const int wn   = wid >> 1;
    const int m0 = blockIdx.y * 128;
    const int n0 = blockIdx.x * BROWS;

    float acc[4][NF][4];
#pragma unroll
    for (int mi = 0; mi < 4; mi++)
#pragma unroll
        for (int ni = 0; ni < NF; ni++)
#pragma unroll
            for (int r = 0; r < 4; r++) acc[mi][ni][r] = 0.f;

    auto loadChunk = [&](int ck, int st) {
        const int k0 = ck << 5;
        const uint32_t stb = base_b + st * (STAGE_W * 4);
#pragma unroll
        for (int j = 0; j < 4; j++) {
            int idx = tid + 256 * j;
            int half = idx >> 9;
            int row = (idx >> 2) & 127;
            int part = idx & 3;
            const bf16* base = half ? Al : Ah;
            cpa16(stb + ((half ? OFF_AL : 0) + row * GSTRIDE_W + part * 4) * 4,
                  base + (size_t)(m0 + row) * K + k0 + part * 8);
        }
#pragma unroll
        for (int j = 0; j < (BROWS * 8 + 255) / 256; j++) {
            int idx = tid + 256 * j;
            if (idx < BROWS * 8) {
                int half = idx >= BROWS * 4;
                int i2 = half ? idx - BROWS * 4 : idx;
                int row = i2 >> 2, part = i2 & 3;
                const bf16* base = half ? Bl : Bh;
                cpa16(stb + ((half ? OFF_BL : OFF_BH) + row * GSTRIDE_W + part * 4) * 4,
                      base + (size_t)(n0 + row) * K + k0 + part * 8);
            }
        }
    };

    auto compute = [&](int st) {
        uint32_t* sAh = smw + st * STAGE_W;
        uint32_t* sAl = sAh + OFF_AL;
        uint32_t* sBh = sAh + OFF_BH;
        uint32_t* sBl = sAh + OFF_BL;
#pragma unroll
        for (int ks = 0; ks < 2; ks++) {
            const int kw = ks * 8;
            uint32_t bh[NF][2], bl[NF][2];
#pragma unroll
            for (int ni = 0; ni < NF; ni++) {
                int base = (wn * 8 * NF + ni * 8 + g) * GSTRIDE_W + kw + c;
                bh[ni][0] = sBh[base]; bh[ni][1] = sBh[base + 4];
                bl[ni][0] = sBl[base]; bl[ni][1] = sBl[base + 4];
            }
#pragma unroll
            for (int mi = 0; mi < 4; mi++) {
                int base = (wm * 64 + mi * 16 + g) * GSTRIDE_W + kw + c;
                uint32_t ah[4], al[4];
                ah[0] = sAh[base];       ah[1] = sAh[base + 8 * GSTRIDE_W];
                ah[2] = sAh[base + 4];   ah[3] = sAh[base + 4 + 8 * GSTRIDE_W];
                al[0] = sAl[base];       al[1] = sAl[base + 8 * GSTRIDE_W];
                al[2] = sAl[base + 4];   al[3] = sAl[base + 4 + 8 * GSTRIDE_W];
#pragma unroll
                for (int ni = 0; ni < NF; ni++) mma16816(acc[mi][ni], ah, bh[ni]);
#pragma unroll
                for (int ni = 0; ni < NF; ni++) mma16816(acc[mi][ni], al, bh[ni]);
#pragma unroll
                for (int ni = 0; ni < NF; ni++) mma16816(acc[mi][ni], ah, bl[ni]);
            }
        }
    };

    const int nch = K >> 5;

    loadChunk(0, 0);
    CP_COMMIT();
    if (nch > 1) loadChunk(1, 1);
    CP_COMMIT();

    for (int ck = 0; ck < nch; ck++) {
        CP_WAIT(1);
        __syncthreads();
        compute(ck & 1);
        __syncthreads();
        if (ck + 2 < nch) loadChunk(ck + 2, ck & 1);
        CP_COMMIT();
    }

#pragma unroll
    for (int mi = 0; mi < 4; mi++) {
#pragma unroll
        for (int ni = 0; ni < NF; ni++) {
            int row = m0 + wm * 64 + mi * 16 + g;
            int col = n0 + wn * 8 * NF + ni * 8 + 2 * c;
            if (col < Ns) {
                float bx = 0.f, by = 0.f;
                if (bias != nullptr) { bx = bias[col]; by = bias[col + 1]; }
                float2 o0, o1;
                o0.x = acc[mi][ni][0] + bx; o0.y = acc[mi][ni][1] + by;
                o1.x = acc[mi][ni][2] + bx; o1.y = acc[mi][ni][3] + by;
                if (RELU) {
                    o0.x = fmaxf(o0.x, 0.f); o0.y = fmaxf(o0.y, 0.f);
                    o1.x = fmaxf(o1.x, 0.f); o1.y = fmaxf(o1.y, 0.f);
                }
                if (SPLITOUT) {
                    uint32_t h0, l0, h1, l1;
                    split_pack2(o0.x, o0.y, h0, l0);
                    split_pack2(o1.x, o1.y, h1, l1);
                    size_t w0 = ((size_t)row * Ns + col) >> 1;
                    size_t w1 = ((size_t)(row + 8) * Ns + col) >> 1;
                    ((uint32_t*)Ch)[w0] = h0; ((uint32_t*)Cl)[w0] = l0;
                    ((uint32_t*)Ch)[w1] = h1; ((uint32_t*)Cl)[w1] = l1;
                } else {
                    *(float2*)(C + (size_t)row * Ns + col) = o0;
                    *(float2*)(C + (size_t)(row + 8) * Ns + col) = o1;
                }
            }
        }
    }
}
#define GEMM_SMEM_B(NF) (2 * (5120 + 2 * (32*(NF)) * GSTRIDE_W) * 4)

// =====================================================================
// Flash attention (frozen — R12 structure)
// =====================================================================
#define AT_STG_W   22528
#define AT_YL_OFF  6912
#define AT_SH_OFF  13824
#define AT_SL_OFF  18176
#define ATTN_SMEM_BYTES (2 * AT_STG_W * 4)   // 180224

__global__ __launch_bounds__(256) void attn_kernel(
    const bf16* __restrict__ qh_g, const bf16* __restrict__ ql_g,
    const bf16* __restrict__ yh_g, const bf16* __restrict__ yl_g,
    const bf16* __restrict__ sh_g, const bf16* __restrict__ sl_g,
    bf16* __restrict__ ath, bf16* __restrict__ atl)
{
    extern __shared__ uint32_t smw[];
    const uint32_t base_b = smem_u32(smw);
    const int tid  = threadIdx.x;
    const int wid  = tid >> 5;
    const int lane = tid & 31;
    const int g    = lane >> 2;
    const int c    = lane & 3;
    const int bb   = blockIdx.y;
    const int q0   = blockIdx.x * 128;
    const int q0w  = wid * 16;
    const size_t bbS = (size_t)bb * SEQ;

    const int qrow_off = (q0w + (lane & 15)) * 108 + (lane >> 4) * 4;
    const int yrow_off = (8 * (lane >> 4) + (lane & 7)) * 108 + ((lane >> 3) & 1) * 4;
    const int srow_off = (((lane >> 3) & 1) * 8 + (lane & 7)) * 68 + (lane >> 4) * 4;

#pragma unroll
    for (int j = 0; j < 26; j++) {
        int idx = tid + 256 * j;
        int half = idx >= 3328;
        int i2 = half ? idx - 3328 : idx;
        int row = i2 / 26, ch = i2 - row * 26;
        const bf16* src = (half ? ql_g : qh_g) + (bbS + q0 + row) * QP + ch * 8;
        uint32_t dst = base_b + ((half ? AT_SH_OFF : 0) + row * 108 + ch * 4) * 4;
        cpa16(dst, src);
    }
    CP_COMMIT();
    CP_WAIT(0);
    __syncthreads();

    uint32_t qrh[13][4], qrl[13][4];
    {
        const uint32_t qh_b = base_b + qrow_off * 4;
        const uint32_t ql_b = base_b + (AT_SH_OFF + qrow_off) * 4;
#pragma unroll
        for (int h = 0; h < 13; h++) {
            ldmx4(qrh[h], qh_b + h * 32);
            ldmx4(qrl[h], ql_b + h * 32);
        }
    }
    __syncthreads();

    float m0v = -1e30f, m1v = -1e30f, l0v = 0.f, l1v = 0.f;
    float acc[16][4];
#pragma unroll
    for (int t = 0; t < 16; t++)
#pragma unroll
        for (int r = 0; r < 4; r++) acc[t][r] = 0.f;

    auto loadTile = [&](int s0, int stg) {
        const uint32_t sb = base_b + stg * (AT_STG_W * 4);
#pragma unroll
        for (int j = 0; j < 13; j++) {
            int idx = tid + 256 * j;
            int half = idx >= 1664;
            int i2 = half ? idx - 1664 : idx;
            int row = i2 / 26, ch = i2 - row * 26;
            const bf16* src = (half ? yl_g : yh_g) + (bbS + s0 + row) * QP + ch * 8;
            cpa16(sb + ((half ? AT_YL_OFF : 0) + row * 108 + ch * 4) * 4, src);
        }
#pragma unroll
        for (int j = 0; j < 8; j++) {
            int idx = tid + 256 * j;
            int half = idx >= 1024;
            int i2 = half ? idx - 1024 : idx;
            int row = i2 >> 4, ch = i2 & 15;
            const bf16* src = (half ? sl_g : sh_g) + (bbS + s0 + row) * VDIM + ch * 8;
            cpa16(sb + ((half ? AT_SL_OFF : AT_SH_OFF) + row * 68 + ch * 4) * 4, src);
        }
    };

    loadTile(0, 0);
    CP_COMMIT();

    for (int t = 0; t < 16; t++) {
        __syncthreads();
        if (t + 1 < 16) loadTile((t + 1) * 64, (t + 1) & 1);
        CP_COMMIT();
        CP_WAIT(1);
        __syncthreads();

        const int stg = t & 1;
        const uint32_t yh_b = base_b + (stg * AT_STG_W + yrow_off) * 4;
        const uint32_t yl_b = yh_b + AT_YL_OFF * 4;
        const uint32_t sh_b = base_b + (stg * AT_STG_W + AT_SH_OFF + srow_off) * 4;
        const uint32_t sl_b = base_b + (stg * AT_STG_W + AT_SL_OFF + srow_off) * 4;

        float sc[8][4];
#pragma unroll
        for (int t8 = 0; t8 < 8; t8++)
#pragma unroll
            for (int r = 0; r < 4; r++) sc[t8][r] = 0.f;

#pragma unroll
        for (int h = 0; h < 13; h++) {
            uint32_t bh[4][4], bl[4][4];
#pragma unroll
            for (int t2 = 0; t2 < 4; t2++) {
                ldmx4(bh[t2], yh_b + (t2 * 1728 + h * 8) * 4);
                ldmx4(bl[t2], yl_b + (t2 * 1728 + h * 8) * 4);
            }
#pragma unroll
            for (int t2 = 0; t2 < 4; t2++) {
                mma2(sc[2 * t2],     qrh[h], bh[t2][0], bh[t2][1]);
                mma2(sc[2 * t2 + 1], qrh[h], bh[t2][2], bh[t2][3]);
            }
#pragma unroll
            for (int t2 = 0; t2 < 4; t2++) {
                mma2(sc[2 * t2],     qrl[h], bh[t2][0], bh[t2][1]);
                mma2(sc[2 * t2 + 1], qrl[h], bh[t2][2], bh[t2][3]);
            }
#pragma unroll
            for (int t2 = 0; t2 < 4; t2++) {
                mma2(sc[2 * t2],     qrh[h], bl[t2][0], bl[t2][1]);
                mma2(sc[2 * t2 + 1], qrh[h], bl[t2][2], bl[t2][3]);
            }
        }

        float mx0 = sc[0][0], mx1 = sc[0][2];
#pragma unroll
        for (int t8 = 0; t8 < 8; t8++) {
            mx0 = fmaxf(mx0, fmaxf(sc[t8][0], sc[t8][1]));
            mx1 = fmaxf(mx1, fmaxf(sc[t8][2], sc[t8][3]));
        }
        mx0 = fmaxf(mx0, __shfl_xor_sync(0xffffffffu, mx0, 1));
        mx0 = fmaxf(mx0, __shfl_xor_sync(0xffffffffu, mx0, 2));
        mx1 = fmaxf(mx1, __shfl_xor_sync(0xffffffffu, mx1, 1));
        mx1 = fmaxf(mx1, __shfl_xor_sync(0xffffffffu, mx1, 2));
        float mn0 = fmaxf(m0v, mx0), mn1 = fmaxf(m1v, mx1);
        float ts0 = 0.f, ts1 = 0.f;
#pragma unroll
        for (int t8 = 0; t8 < 8; t8++) {
            sc[t8][0] = __expf(sc[t8][0] - mn0); ts0 += sc[t8][0];
            sc[t8][1] = __expf(sc[t8][1] - mn0); ts0 += sc[t8][1];
            sc[t8][2] = __expf(sc[t8][2] - mn1); ts1 += sc[t8][2];
            sc[t8][3] = __expf(sc[t8][3] - mn1); ts1 += sc[t8][3];
        }
        ts0 += __shfl_xor_sync(0xffffffffu, ts0, 1);
        ts0 += __shfl_xor_sync(0xffffffffu, ts0, 2);
        ts1 += __shfl_xor_sync(0xffffffffu, ts1, 1);
        ts1 += __shfl_xor_sync(0xffffffffu, ts1, 2);
        float f0 = __expf(m0v - mn0), f1 = __expf(m1v - mn1);
        l0v = l0v * f0 + ts0; l1v = l1v * f1 + ts1;
        m0v = mn0; m1v = mn1;
#pragma unroll
        for (int t16 = 0; t16 < 16; t16++) {
            acc[t16][0] *= f0; acc[t16][1] *= f0;
            acc[t16][2] *= f1; acc[t16][3] *= f1;
        }

#pragma unroll
        for (int h = 0; h < 4; h++) {
            uint32_t pah[4], pal[4];
            split_pack2(sc[2 * h][0],     sc[2 * h][1],     pah[0], pal[0]);
            split_pack2(sc[2 * h][2],     sc[2 * h][3],     pah[1], pal[1]);
            split_pack2(sc[2 * h + 1][0], sc[2 * h + 1][1], pah[2], pal[2]);
            split_pack2(sc[2 * h + 1][2], sc[2 * h + 1][3], pah[3], pal[3]);
#pragma unroll
            for (int t2 = 0; t2 < 8; t2++) {
                uint32_t bh[4], bl[4];
                ldmx4t(bh, sh_b + (h * 1088 + t2 * 8) * 4);
                ldmx4t(bl, sl_b + (h * 1088 + t2 * 8) * 4);
                mma2(acc[2 * t2],     pah, bh[0], bh[1]);
                mma2(acc[2 * t2 + 1], pah, bh[2], bh[3]);
                mma2(acc[2 * t2],     pal, bh[0], bh[1]);
                mma2(acc[2 * t2 + 1], pal, bh[2], bh[3]);
                mma2(acc[2 * t2],     pah, bl[0], bl[1]);
                mma2(acc[2 * t2 + 1], pah, bl[2], bl[3]);
            }
        }
    }

    float inv0 = 1.f / l0v, inv1 = 1.f / l1v;
    int row0 = q0 + q0w + g;
    size_t b0 = (bbS + row0) * VDIM;
    size_t b1 = b0 + 8 * VDIM;
    uint32_t* ah32 = (uint32_t*)ath;
    uint32_t* al32 = (uint32_t*)atl;
#pragma unroll
    for (int t = 0; t < 16; t++) {
        int col = 8 * t + 2 * c;
        uint32_t h0, l0, h1, l1;
        split_pack2(acc[t][0] * inv0, acc[t][1] * inv0, h0, l0);
        split_pack2(acc[t][2] * inv1, acc[t][3] * inv1, h1, l1);
        ah32[(b0 + col) >> 1] = h0; al32[(b0 + col) >> 1] = l0;
        ah32[(b1 + col) >> 1] = h1; al32[(b1 + col) >> 1] = l1;
    }
}

// =====================================================================
// launcher — parallel attention halves across both streams
// =====================================================================
extern "C" void kernel_launch(void* const* d_in, const int* in_sizes, int n_in,
                              void* d_out, int out_size)
{
    (void)in_sizes; (void)n_in; (void)out_size;
    const float* mem = (const float*)d_in[0];
    const float* srl = (const float*)d_in[1];
    const float* emb = (const float*)d_in[2];
    const float* W1  = (const float*)d_in[4];
    const float* b1  = (const float*)d_in[5];
    const float* W2  = (const float*)d_in[6];
    const float* b2  = (const float*)d_in[7];
    const float* mat = (const float*)d_in[8];
    const float* Wp  = (const float*)d_in[9];
    const float* bp  = (const float*)d_in[10];
    float* outp = (float*)d_out;

#define SYM(v, s) cudaGetSymbolAddress((void**)&v, s)
    bf16 *embh, *embl, *memh, *meml, *srlh, *srll;
    bf16 *hh, *hl, *qh, *ql, *yh, *yl, *ath, *atl;
    bf16 *w1th, *w1tl, *w2th, *w2tl, *math_, *matl, *wph, *wpl;
    float *b1p, *b2p;
    SYM(embh, g_embh); SYM(embl, g_embl);
    SYM(memh, g_memh); SYM(meml, g_meml);
    SYM(srlh, g_srlh); SYM(srll, g_srll);
    SYM(hh, g_hh); SYM(hl, g_hl);
    SYM(qh, g_qh); SYM(ql, g_ql);
    SYM(yh, g_yh); SYM(yl, g_yl);
    SYM(ath, g_ath); SYM(atl, g_atl);
    SYM(w1th, g_w1th); SYM(w1tl, g_w1tl);
    SYM(w2th, g_w2th); SYM(w2tl, g_w2tl);
    SYM(math_, g_math); SYM(matl, g_matl);
    SYM(wph, g_wph); SYM(wpl, g_wpl);
    SYM(b1p, g_b1p); SYM(b2p, g_b2p);
#undef SYM

    static cudaStream_t s2 = nullptr;
    static cudaEvent_t evF = nullptr, evQa = nullptr, evY = nullptr, evS2 = nullptr;
    if (s2 == nullptr) {
        cudaStreamCreateWithFlags(&s2, cudaStreamNonBlocking);
        cudaEventCreateWithFlags(&evF, cudaEventDisableTiming);
        cudaEventCreateWithFlags(&evQa, cudaEventDisableTiming);
        cudaEventCreateWithFlags(&evY, cudaEventDisableTiming);
        cudaEventCreateWithFlags(&evS2, cudaEventDisableTiming);
        cudaFuncSetAttribute(attn_kernel,
                             cudaFuncAttributeMaxDynamicSharedMemorySize, ATTN_SMEM_BYTES);
        cudaFuncSetAttribute(gemm_bf16<5, true, true>,
                             cudaFuncAttributeMaxDynamicSharedMemorySize, GEMM_SMEM_B(5));
        cudaFuncSetAttribute(gemm_bf16<4, true, true>,
                             cudaFuncAttributeMaxDynamicSharedMemorySize, GEMM_SMEM_B(4));
        cudaFuncSetAttribute(gemm_bf16<4, false, true>,
                             cudaFuncAttributeMaxDynamicSharedMemorySize, GEMM_SMEM_B(4));
        cudaFuncSetAttribute(gemm_bf16<4, false, false>,
                             cudaFuncAttributeMaxDynamicSharedMemorySize, GEMM_SMEM_B(4));
    }

    // fork
    cudaEventRecord(evF, 0);
    cudaStreamWaitEvent(s2, evF, 0);

    // ---- s2: mem/mat/srl/Wp prep, G3a, G3b, record evY ----
    {
        long long n2 = (long long)MTOT * MEMP / 2;
        split_pad2<<<(unsigned)((n2 + 255) / 256), 256, 0, s2>>>(mem, memh, meml, n2, DDIM, MEMP);
        tsplit<<<(MATNP * MEMP + 255) / 256, 256, 0, s2>>>(mat, math_, matl, DDIM, DDIM, MEMP, MATNP);
        n2 = (long long)MTOT * VDIM / 2;
        split_pad2<<<(unsigned)((n2 + 255) / 256), 256, 0, s2>>>(srl, srlh, srll, n2, VDIM, VDIM);
        n2 = (long long)VDIM * VDIM / 2;
        split_pad2<<<(unsigned)((n2 + 255) / 256), 256, 0, s2>>>(Wp, wph, wpl, n2, VDIM, VDIM);
        gemm_bf16<4, false, true><<<dim3(2, 128), 256, GEMM_SMEM_B(4), s2>>>(
            memh, meml, math_, matl, nullptr, nullptr, yh, yl, QP, MEMP);
        gemm_bf16<4, false, true><<<dim3(2, 128), 256, GEMM_SMEM_B(4), s2>>>(
            memh + (size_t)HM * MEMP, meml + (size_t)HM * MEMP, math_, matl,
            nullptr, nullptr, yh + (size_t)HM * QP, yl + (size_t)HM * QP, QP, MEMP);
        cudaEventRecord(evY, s2);
    }

    // ---- s0: prep_w12, embsplit-a, G1a, embsplit-b, G2a (evQa), G1b, G2b ----
    {
        prep_w12<<<(WP_D + 255) / 256, 256>>>(W1, W2, b1, b2,
                                              w1th, w1tl, w2th, w2tl, b1p, b2p);
        long long n2h = (long long)HM * EMB / 2;
        split_pad2<<<(unsigned)((n2h + 255) / 256), 256>>>(emb, embh, embl, n2h, EMB, EMB);
        // G1a
        gemm_bf16<5, true, true><<<dim3(2, 128), 256, GEMM_SMEM_B(5)>>>(
            embh, embl, w1th, w1tl, b1p, nullptr, hh, hl, HP, EMB);
        // embsplit-b (overlaps nothing critical; fills slack before G1b)
        split_pad2<<<(unsigned)((n2h + 255) / 256), 256>>>(
            emb + (size_t)HM * EMB, embh + (size_t)HM * EMB, embl + (size_t)HM * EMB,
            n2h, EMB, EMB);
        // G2a
        gemm_bf16<4, true, true><<<dim3(2, 128), 256, GEMM_SMEM_B(4)>>>(
            hh, hl, w2th, w2tl, b2p, nullptr, qh, ql, QP, HP);
        cudaEventRecord(evQa, 0);
        // G1b
        gemm_bf16<5, true, true><<<dim3(2, 128), 256, GEMM_SMEM_B(5)>>>(
            embh + (size_t)HM * EMB, embl + (size_t)HM * EMB, w1th, w1tl, b1p,
            nullptr, hh + (size_t)HM * HP, hl + (size_t)HM * HP, HP, EMB);
        // G2b
        gemm_bf16<4, true, true><<<dim3(2, 128), 256, GEMM_SMEM_B(4)>>>(
            hh + (size_t)HM * HP, hl + (size_t)HM * HP, w2th, w2tl, b2p,
            nullptr, qh + (size_t)HM * QP, ql + (size_t)HM * QP, QP, HP);
    }

    // ---- s2: attnA (after G2a via evQa; y/srl already local), then G5a ----
    {
        cudaStreamWaitEvent(s2, evQa, 0);
        attn_kernel<<<dim3(SEQ / 128, HB), 256, ATTN_SMEM_BYTES, s2>>>(
            qh, ql, yh, yl, srlh, srll, ath, atl);
        gemm_bf16<4, false, false><<<dim3(1, 128), 256, GEMM_SMEM_B(4), s2>>>(
            ath, atl, wph, wpl, bp, outp, nullptr, nullptr, VDIM, VDIM);
        cudaEventRecord(evS2, s2);
    }

    // ---- s0: attnB (after G2b, y/srl/Wp via evY), then G5b; join s2 ----
    cudaStreamWaitEvent(0, evY, 0);
    attn_kernel<<<dim3(SEQ / 128, HB), 256, ATTN_SMEM_BYTES>>>(
        qh + (size_t)HM * QP,   ql + (size_t)HM * QP,
        yh + (size_t)HM * QP,   yl + (size_t)HM * QP,
        srlh + (size_t)HM * VDIM, srll + (size_t)HM * VDIM,
        ath + (size_t)HM * VDIM,  atl + (size_t)HM * VDIM);
    gemm_bf16<4, false, false><<<dim3(1, 128), 256, GEMM_SMEM_B(4)>>>(
        ath + (size_t)HM * VDIM, atl + (size_t)HM * VDIM, wph, wpl, bp,
        outp + (size_t)HM * VDIM, nullptr, nullptr, VDIM, VDIM);
    // join side stream back into capture-origin stream
    cudaStreamWaitEvent(0, evS2, 0);
}

// round 16
// speedup vs baseline: 1.0358x; 1.0358x over previous
#include <cuda_runtime.h>
#include <cuda_bf16.h>
#include <cstdint>
#include <cstddef>

// Problem constants
#define BATCH 32
#define SEQ   1024
#define VDIM  128
#define EMB   768
#define H1    300
#define DDIM  200
#define MTOT  (BATCH*SEQ)   // 32768
#define HM    (MTOT/2)      // 16384 (per pipeline half)
#define HB    (BATCH/2)     // 16 batches per half

// padded dims
#define HP    320
#define QP    208
#define MEMP  224
#define W1NP  320
#define W2NP  256
#define MATNP 256

typedef __nv_bfloat16 bf16;

// ---------------- helpers ----------------
__device__ __forceinline__ uint32_t pack_bf16(bf16 lo16, bf16 hi16) {
    __nv_bfloat162 t(lo16, hi16);
    return *(uint32_t*)&t;
}
__device__ __forceinline__ void split_bf16(float v, bf16& h, bf16& l) {
    h = __float2bfloat16(v);
    l = __float2bfloat16(v - __bfloat162float(h));
}
__device__ __forceinline__ void split_pack2(float x, float y, uint32_t& hi, uint32_t& lo) {
    bf16 hx, lx, hy, ly;
    split_bf16(x, hx, lx);
    split_bf16(y, hy, ly);
    hi = pack_bf16(hx, hy);
    lo = pack_bf16(lx, ly);
}
__device__ __forceinline__ void mma16816(float* d, const uint32_t* a, const uint32_t* b) {
    asm volatile(
        "mma.sync.aligned.m16n8k16.row.col.f32.bf16.bf16.f32 "
        "{%0,%1,%2,%3}, {%4,%5,%6,%7}, {%8,%9}, {%0,%1,%2,%3};"
        : "+f"(d[0]), "+f"(d[1]), "+f"(d[2]), "+f"(d[3])
        : "r"(a[0]), "r"(a[1]), "r"(a[2]), "r"(a[3]), "r"(b[0]), "r"(b[1]));
}
__device__ __forceinline__ void mma2(float* d, const uint32_t* a, uint32_t b0, uint32_t b1) {
    asm volatile(
        "mma.sync.aligned.m16n8k16.row.col.f32.bf16.bf16.f32 "
        "{%0,%1,%2,%3}, {%4,%5,%6,%7}, {%8,%9}, {%0,%1,%2,%3};"
        : "+f"(d[0]), "+f"(d[1]), "+f"(d[2]), "+f"(d[3])
        : "r"(a[0]), "r"(a[1]), "r"(a[2]), "r"(a[3]), "r"(b0), "r"(b1));
}
__device__ __forceinline__ uint32_t smem_u32(const void* p) {
    uint32_t a;
    asm("{ .reg .u64 t; cvta.to.shared.u64 t, %1; cvt.u32.u64 %0, t; }"
        : "=r"(a) : "l"(p));
    return a;
}
__device__ __forceinline__ void ldmx4(uint32_t* r, uint32_t addr) {
    asm volatile("ldmatrix.sync.aligned.m8n8.x4.shared.b16 {%0,%1,%2,%3}, [%4];"
        : "=r"(r[0]), "=r"(r[1]), "=r"(r[2]), "=r"(r[3]) : "r"(addr));
}
__device__ __forceinline__ void ldmx4t(uint32_t* r, uint32_t addr) {
    asm volatile("ldmatrix.sync.aligned.m8n8.x4.trans.shared.b16 {%0,%1,%2,%3}, [%4];"
        : "=r"(r[0]), "=r"(r[1]), "=r"(r[2]), "=r"(r[3]) : "r"(addr));
}
__device__ __forceinline__ void cpa16(uint32_t dst, const void* src) {
    asm volatile("cp.async.cg.shared.global [%0], [%1], 16;" :: "r"(dst), "l"(src));
}
#define CP_COMMIT() asm volatile("cp.async.commit_group;" ::: "memory")
#define CP_WAIT(n)  asm volatile("cp.async.wait_group %0;" :: "n"(n) : "memory")

// ---------------- static scratch (bf16 hi/lo pairs) ----------------
__device__ __align__(128) bf16 g_embh[(size_t)MTOT * EMB],  g_embl[(size_t)MTOT * EMB];
__device__ __align__(128) bf16 g_memh[(size_t)MTOT * MEMP], g_meml[(size_t)MTOT * MEMP];
__device__ __align__(128) bf16 g_srlh[(size_t)MTOT * VDIM], g_srll[(size_t)MTOT * VDIM];
__device__ __align__(128) bf16 g_hh[(size_t)MTOT * HP],     g_hl[(size_t)MTOT * HP];
__device__ __align__(128) bf16 g_qh[(size_t)MTOT * QP],     g_ql[(size_t)MTOT * QP];
__device__ __align__(128) bf16 g_yh[(size_t)MTOT * QP],     g_yl[(size_t)MTOT * QP];
__device__ __align__(128) bf16 g_ath[(size_t)MTOT * VDIM],  g_atl[(size_t)MTOT * VDIM];
__device__ __align__(128) bf16 g_w1th[W1NP * EMB],  g_w1tl[W1NP * EMB];
__device__ __align__(128) bf16 g_w2th[W2NP * HP],   g_w2tl[W2NP * HP];
__device__ __align__(128) bf16 g_math[MATNP * MEMP], g_matl[MATNP * MEMP];
__device__ __align__(128) bf16 g_wph[VDIM * VDIM],  g_wpl[VDIM * VDIM];
__device__ __align__(128) float g_b1p[HP];
__device__ __align__(128) float g_b2p[QP];

// ---------------- prep kernels ----------------
__global__ void split_pad2(const float* __restrict__ in, bf16* __restrict__ oh,
                           bf16* __restrict__ ol, long long n2, int C, int CP)
{
    long long i2 = (long long)blockIdx.x * blockDim.x + threadIdx.x;
    if (i2 >= n2) return;
    int cp2 = CP >> 1;
    long long r = i2 / cp2;
    int c2 = (int)(i2 - r * cp2) * 2;
    float x = 0.f, y = 0.f;
    if (c2 + 1 < C) {
        float2 v = *(const float2*)(in + r * C + c2);
        x = v.x; y = v.y;
    } else if (c2 < C) {
        x = in[r * C + c2];
    }
    uint32_t h, l;
    split_pack2(x, y, h, l);
    ((uint32_t*)oh)[(r * CP + c2) >> 1] = h;
    ((uint32_t*)ol)[(r * CP + c2) >> 1] = l;
}

__global__ void tsplit(const float* __restrict__ in, bf16* __restrict__ oh,
                       bf16* __restrict__ ol, int K, int N, int KP, int NP)
{
    int i = blockIdx.x * blockDim.x + threadIdx.x;
    if (i >= NP * KP) return;
    int n = i / KP, k = i - n * KP;
    float v = (n < N && k < K) ? in[(size_t)k * N + n] : 0.f;
    bf16 h, l;
    split_bf16(v, h, l);
    oh[i] = h; ol[i] = l;
}

#define WP_A (W1NP * EMB)
#define WP_B (WP_A + W2NP * HP)
#define WP_C (WP_B + HP)
#define WP_D (WP_C + QP)
__global__ void prep_w12(
    const float* __restrict__ W1, const float* __restrict__ W2,
    const float* __restrict__ b1, const float* __restrict__ b2,
    bf16* __restrict__ w1th, bf16* __restrict__ w1tl,
    bf16* __restrict__ w2th, bf16* __restrict__ w2tl,
    float* __restrict__ b1p, float* __restrict__ b2p)
{
    int i = blockIdx.x * blockDim.x + threadIdx.x;
    if (i < WP_A) {
        int n = i / EMB, k = i - n * EMB;
        float v = (n < H1) ? W1[(size_t)k * H1 + n] : 0.f;
        bf16 h, l; split_bf16(v, h, l);
        w1th[i] = h; w1tl[i] = l;
    } else if (i < WP_B) {
        int j = i - WP_A;
        int n = j / HP, k = j - n * HP;
        float v = (n < DDIM && k < H1) ? W2[(size_t)k * DDIM + n] : 0.f;
        bf16 h, l; split_bf16(v, h, l);
        w2th[j] = h; w2tl[j] = l;
    } else if (i < WP_C) {
        int j = i - WP_B;
        b1p[j] = (j < H1) ? b1[j] : 0.f;
    } else if (i < WP_D) {
        int j = i - WP_C;
        b2p[j] = (j < DDIM) ? b2[j] : 0.f;
    }
}

// =====================================================================
// bf16 pre-split GEMM, templated on NF (frozen)
// =====================================================================
#define GSTRIDE_W 20

template<int NF, bool RELU, bool SPLITOUT>
__global__ __launch_bounds__(256) void gemm_bf16(
    const bf16* __restrict__ Ah, const bf16* __restrict__ Al,
    const bf16* __restrict__ Bh, const bf16* __restrict__ Bl,
    const float* __restrict__ bias,
    float* __restrict__ C, bf16* __restrict__ Ch, bf16* __restrict__ Cl,
    int Ns, int K)
{
    constexpr int BROWS   = 32 * NF;
    constexpr int STAGE_W = 5120 + 2 * BROWS * GSTRIDE_W;
    constexpr int OFF_AL  = 2560;
    constexpr int OFF_BH  = 5120;
    constexpr int OFF_BL  = 5120 + BROWS * GSTRIDE_W;

    extern __shared__ uint32_t smw[];
    const uint32_t base_b = smem_u32(smw);

    const int tid  = threadIdx.x;
    const int wid  = tid >> 5;
    const int lane = tid & 31;
    const int g    = lane >> 2;
    const int c    = lane & 3;
    const int wm   = wid & 1;
    const int wn   = wid >> 1;
    const int m0 = blockIdx.y * 128;
    const int n0 = blockIdx.x * BROWS;

    float acc[4][NF][4];
#pragma unroll
    for (int mi = 0; mi < 4; mi++)
#pragma unroll
        for (int ni = 0; ni < NF; ni++)
#pragma unroll
            for (int r = 0; r < 4; r++) acc[mi][ni][r] = 0.f;

    auto loadChunk = [&](int ck, int st) {
        const int k0 = ck << 5;
        const uint32_t stb = base_b + st * (STAGE_W * 4);
#pragma unroll
        for (int j = 0; j < 4; j++) {
            int idx = tid + 256 * j;
            int half = idx >> 9;
            int row = (idx >> 2) & 127;
            int part = idx & 3;
            const bf16* base = half ? Al : Ah;
            cpa16(stb + ((half ? OFF_AL : 0) + row * GSTRIDE_W + part * 4) * 4,
                  base + (size_t)(m0 + row) * K + k0 + part * 8);
        }
#pragma unroll
        for (int j = 0; j < (BROWS * 8 + 255) / 256; j++) {
            int idx = tid + 256 * j;
            if (idx < BROWS * 8) {
                int half = idx >= BROWS * 4;
                int i2 = half ? idx - BROWS * 4 : idx;
                int row = i2 >> 2, part = i2 & 3;
                const bf16* base = half ? Bl : Bh;
                cpa16(stb + ((half ? OFF_BL : OFF_BH) + row * GSTRIDE_W + part * 4) * 4,
                      base + (size_t)(n0 + row) * K + k0 + part * 8);
            }
        }
    };

    auto compute = [&](int st) {
        uint32_t* sAh = smw + st * STAGE_W;
        uint32_t* sAl = sAh + OFF_AL;
        uint32_t* sBh = sAh + OFF_BH;
        uint32_t* sBl = sAh + OFF_BL;
#pragma unroll
        for (int ks = 0; ks < 2; ks++) {
            const int kw = ks * 8;
            uint32_t bh[NF][2], bl[NF][2];
#pragma unroll
            for (int ni = 0; ni < NF; ni++) {
                int base = (wn * 8 * NF + ni * 8 + g) * GSTRIDE_W + kw + c;
                bh[ni][0] = sBh[base]; bh[ni][1] = sBh[base + 4];
                bl[ni][0] = sBl[base]; bl[ni][1] = sBl[base + 4];
            }
#pragma unroll
            for (int mi = 0; mi < 4; mi++) {
                int base = (wm * 64 + mi * 16 + g) * GSTRIDE_W + kw + c;
                uint32_t ah[4], al[4];
                ah[0] = sAh[base];       ah[1] = sAh[base + 8 * GSTRIDE_W];
                ah[2] = sAh[base + 4];   ah[3] = sAh[base + 4 + 8 * GSTRIDE_W];
                al[0] = sAl[base];       al[1] = sAl[base + 8 * GSTRIDE_W];
                al[2] = sAl[base + 4];   al[3] = sAl[base + 4 + 8 * GSTRIDE_W];
#pragma unroll
                for (int ni = 0; ni < NF; ni++) mma16816(acc[mi][ni], ah, bh[ni]);
#pragma unroll
                for (int ni = 0; ni < NF; ni++) mma16816(acc[mi][ni], al, bh[ni]);
#pragma unroll
                for (int ni = 0; ni < NF; ni++) mma16816(acc[mi][ni], ah, bl[ni]);
            }
        }
    };

    const int nch = K >> 5;

    loadChunk(0, 0);
    CP_COMMIT();
    if (nch > 1) loadChunk(1, 1);
    CP_COMMIT();

    for (int ck = 0; ck < nch; ck++) {
        CP_WAIT(1);
        __syncthreads();
        compute(ck & 1);
        __syncthreads();
        if (ck + 2 < nch) loadChunk(ck + 2, ck & 1);
        CP_COMMIT();
    }

#pragma unroll
    for (int mi = 0; mi < 4; mi++) {
#pragma unroll
        for (int ni = 0; ni < NF; ni++) {
            int row = m0 + wm * 64 + mi * 16 + g;
            int col = n0 + wn * 8 * NF + ni * 8 + 2 * c;
            if (col < Ns) {
                float bx = 0.f, by = 0.f;
                if (bias != nullptr) { bx = bias[col]; by = bias[col + 1]; }
                float2 o0, o1;
                o0.x = acc[mi][ni][0] + bx; o0.y = acc[mi][ni][1] + by;
                o1.x = acc[mi][ni][2] + bx; o1.y = acc[mi][ni][3] + by;
                if (RELU) {
                    o0.x = fmaxf(o0.x, 0.f); o0.y = fmaxf(o0.y, 0.f);
                    o1.x = fmaxf(o1.x, 0.f); o1.y = fmaxf(o1.y, 0.f);
                }
                if (SPLITOUT) {
                    uint32_t h0, l0, h1, l1;
                    split_pack2(o0.x, o0.y, h0, l0);
                    split_pack2(o1.x, o1.y, h1, l1);
                    size_t w0 = ((size_t)row * Ns + col) >> 1;
                    size_t w1 = ((size_t)(row + 8) * Ns + col) >> 1;
                    ((uint32_t*)Ch)[w0] = h0; ((uint32_t*)Cl)[w0] = l0;
                    ((uint32_t*)Ch)[w1] = h1; ((uint32_t*)Cl)[w1] = l1;
                } else {
                    *(float2*)(C + (size_t)row * Ns + col) = o0;
                    *(float2*)(C + (size_t)(row + 8) * Ns + col) = o1;
                }
            }
        }
    }
}
#define GEMM_SMEM_B(NF) (2 * (5120 + 2 * (32*(NF)) * GSTRIDE_W) * 4)

// =====================================================================
// Flash attention (frozen — R12 structure)
// =====================================================================
#define AT_STG_W   22528
#define AT_YL_OFF  6912
#define AT_SH_OFF  13824
#define AT_SL_OFF  18176
#define ATTN_SMEM_BYTES (2 * AT_STG_W * 4)   // 180224

__global__ __launch_bounds__(256) void attn_kernel(
    const bf16* __restrict__ qh_g, const bf16* __restrict__ ql_g,
    const bf16* __restrict__ yh_g, const bf16* __restrict__ yl_g,
    const bf16* __restrict__ sh_g, const bf16* __restrict__ sl_g,
    bf16* __restrict__ ath, bf16* __restrict__ atl)
{
    extern __shared__ uint32_t smw[];
    const uint32_t base_b = smem_u32(smw);
    const int tid  = threadIdx.x;
    const int wid  = tid >> 5;
    const int lane = tid & 31;
    const int g    = lane >> 2;
    const int c    = lane & 3;
    const int bb   = blockIdx.y;
    const int q0   = blockIdx.x * 128;
    const int q0w  = wid * 16;
    const size_t bbS = (size_t)bb * SEQ;

    const int qrow_off = (q0w + (lane & 15)) * 108 + (lane >> 4) * 4;
    const int yrow_off = (8 * (lane >> 4) + (lane & 7)) * 108 + ((lane >> 3) & 1) * 4;
    const int srow_off = (((lane >> 3) & 1) * 8 + (lane & 7)) * 68 + (lane >> 4) * 4;

#pragma unroll
    for (int j = 0; j < 26; j++) {
        int idx = tid + 256 * j;
        int half = idx >= 3328;
        int i2 = half ? idx - 3328 : idx;
        int row = i2 / 26, ch = i2 - row * 26;
        const bf16* src = (half ? ql_g : qh_g) + (bbS + q0 + row) * QP + ch * 8;
        uint32_t dst = base_b + ((half ? AT_SH_OFF : 0) + row * 108 + ch * 4) * 4;
        cpa16(dst, src);
    }
    CP_COMMIT();
    CP_WAIT(0);
    __syncthreads();

    uint32_t qrh[13][4], qrl[13][4];
    {
        const uint32_t qh_b = base_b + qrow_off * 4;
        const uint32_t ql_b = base_b + (AT_SH_OFF + qrow_off) * 4;
#pragma unroll
        for (int h = 0; h < 13; h++) {
            ldmx4(qrh[h], qh_b + h * 32);
            ldmx4(qrl[h], ql_b + h * 32);
        }
    }
    __syncthreads();

    float m0v = -1e30f, m1v = -1e30f, l0v = 0.f, l1v = 0.f;
    float acc[16][4];
#pragma unroll
    for (int t = 0; t < 16; t++)
#pragma unroll
        for (int r = 0; r < 4; r++) acc[t][r] = 0.f;

    auto loadTile = [&](int s0, int stg) {
        const uint32_t sb = base_b + stg * (AT_STG_W * 4);
#pragma unroll
        for (int j = 0; j < 13; j++) {
            int idx = tid + 256 * j;
            int half = idx >= 1664;
            int i2 = half ? idx - 1664 : idx;
            int row = i2 / 26, ch = i2 - row * 26;
            const bf16* src = (half ? yl_g : yh_g) + (bbS + s0 + row) * QP + ch * 8;
            cpa16(sb + ((half ? AT_YL_OFF : 0) + row * 108 + ch * 4) * 4, src);
        }
#pragma unroll
        for (int j = 0; j < 8; j++) {
            int idx = tid + 256 * j;
            int half = idx >= 1024;
            int i2 = half ? idx - 1024 : idx;
            int row = i2 >> 4, ch = i2 & 15;
            const bf16* src = (half ? sl_g : sh_g) + (bbS + s0 + row) * VDIM + ch * 8;
            cpa16(sb + ((half ? AT_SL_OFF : AT_SH_OFF) + row * 68 + ch * 4) * 4, src);
        }
    };

    loadTile(0, 0);
    CP_COMMIT();

    for (int t = 0; t < 16; t++) {
        __syncthreads();
        if (t + 1 < 16) loadTile((t + 1) * 64, (t + 1) & 1);
        CP_COMMIT();
        CP_WAIT(1);
        __syncthreads();

        const int stg = t & 1;
        const uint32_t yh_b = base_b + (stg * AT_STG_W + yrow_off) * 4;
        const uint32_t yl_b = yh_b + AT_YL_OFF * 4;
        const uint32_t sh_b = base_b + (stg * AT_STG_W + AT_SH_OFF + srow_off) * 4;
        const uint32_t sl_b = base_b + (stg * AT_STG_W + AT_SL_OFF + srow_off) * 4;

        float sc[8][4];
#pragma unroll
        for (int t8 = 0; t8 < 8; t8++)
#pragma unroll
            for (int r = 0; r < 4; r++) sc[t8][r] = 0.f;

#pragma unroll
        for (int h = 0; h < 13; h++) {
            uint32_t bh[4][4], bl[4][4];
#pragma unroll
            for (int t2 = 0; t2 < 4; t2++) {
                ldmx4(bh[t2], yh_b + (t2 * 1728 + h * 8) * 4);
                ldmx4(bl[t2], yl_b + (t2 * 1728 + h * 8) * 4);
            }
#pragma unroll
            for (int t2 = 0; t2 < 4; t2++) {
                mma2(sc[2 * t2],     qrh[h], bh[t2][0], bh[t2][1]);
                mma2(sc[2 * t2 + 1], qrh[h], bh[t2][2], bh[t2][3]);
            }
#pragma unroll
            for (int t2 = 0; t2 < 4; t2++) {
                mma2(sc[2 * t2],     qrl[h], bh[t2][0], bh[t2][1]);
                mma2(sc[2 * t2 + 1], qrl[h], bh[t2][2], bh[t2][3]);
            }
#pragma unroll
            for (int t2 = 0; t2 < 4; t2++) {
                mma2(sc[2 * t2],     qrh[h], bl[t2][0], bl[t2][1]);
                mma2(sc[2 * t2 + 1], qrh[h], bl[t2][2], bl[t2][3]);
            }
        }

        float mx0 = sc[0][0], mx1 = sc[0][2];
#pragma unroll
        for (int t8 = 0; t8 < 8; t8++) {
            mx0 = fmaxf(mx0, fmaxf(sc[t8][0], sc[t8][1]));
            mx1 = fmaxf(mx1, fmaxf(sc[t8][2], sc[t8][3]));
        }
        mx0 = fmaxf(mx0, __shfl_xor_sync(0xffffffffu, mx0, 1));
        mx0 = fmaxf(mx0, __shfl_xor_sync(0xffffffffu, mx0, 2));
        mx1 = fmaxf(mx1, __shfl_xor_sync(0xffffffffu, mx1, 1));
        mx1 = fmaxf(mx1, __shfl_xor_sync(0xffffffffu, mx1, 2));
        float mn0 = fmaxf(m0v, mx0), mn1 = fmaxf(m1v, mx1);
        float ts0 = 0.f, ts1 = 0.f;
#pragma unroll
        for (int t8 = 0; t8 < 8; t8++) {
            sc[t8][0] = __expf(sc[t8][0] - mn0); ts0 += sc[t8][0];
            sc[t8][1] = __expf(sc[t8][1] - mn0); ts0 += sc[t8][1];
            sc[t8][2] = __expf(sc[t8][2] - mn1); ts1 += sc[t8][2];
            sc[t8][3] = __expf(sc[t8][3] - mn1); ts1 += sc[t8][3];
        }
        ts0 += __shfl_xor_sync(0xffffffffu, ts0, 1);
        ts0 += __shfl_xor_sync(0xffffffffu, ts0, 2);
        ts1 += __shfl_xor_sync(0xffffffffu, ts1, 1);
        ts1 += __shfl_xor_sync(0xffffffffu, ts1, 2);
        float f0 = __expf(m0v - mn0), f1 = __expf(m1v - mn1);
        l0v = l0v * f0 + ts0; l1v = l1v * f1 + ts1;
        m0v = mn0; m1v = mn1;
#pragma unroll
        for (int t16 = 0; t16 < 16; t16++) {
            acc[t16][0] *= f0; acc[t16][1] *= f0;
            acc[t16][2] *= f1; acc[t16][3] *= f1;
        }

#pragma unroll
        for (int h = 0; h < 4; h++) {
            uint32_t pah[4], pal[4];
            split_pack2(sc[2 * h][0],     sc[2 * h][1],     pah[0], pal[0]);
            split_pack2(sc[2 * h][2],     sc[2 * h][3],     pah[1], pal[1]);
            split_pack2(sc[2 * h + 1][0], sc[2 * h + 1][1], pah[2], pal[2]);
            split_pack2(sc[2 * h + 1][2], sc[2 * h + 1][3], pah[3], pal[3]);
#pragma unroll
            for (int t2 = 0; t2 < 8; t2++) {
                uint32_t bh[4], bl[4];
                ldmx4t(bh, sh_b + (h * 1088 + t2 * 8) * 4);
                ldmx4t(bl, sl_b + (h * 1088 + t2 * 8) * 4);
                mma2(acc[2 * t2],     pah, bh[0], bh[1]);
                mma2(acc[2 * t2 + 1], pah, bh[2], bh[3]);
                mma2(acc[2 * t2],     pal, bh[0], bh[1]);
                mma2(acc[2 * t2 + 1], pal, bh[2], bh[3]);
                mma2(acc[2 * t2],     pah, bl[0], bl[1]);
                mma2(acc[2 * t2 + 1], pah, bl[2], bl[3]);
            }
        }
    }

    float inv0 = 1.f / l0v, inv1 = 1.f / l1v;
    int row0 = q0 + q0w + g;
    size_t b0 = (bbS + row0) * VDIM;
    size_t b1 = b0 + 8 * VDIM;
    uint32_t* ah32 = (uint32_t*)ath;
    uint32_t* al32 = (uint32_t*)atl;
#pragma unroll
    for (int t = 0; t < 16; t++) {
        int col = 8 * t + 2 * c;
        uint32_t h0, l0, h1, l1;
        split_pack2(acc[t][0] * inv0, acc[t][1] * inv0, h0, l0);
        split_pack2(acc[t][2] * inv1, acc[t][3] * inv1, h1, l1);
        ah32[(b0 + col) >> 1] = h0; al32[(b0 + col) >> 1] = l0;
        ah32[(b1 + col) >> 1] = h1; al32[(b1 + col) >> 1] = l1;
    }
}

// =====================================================================
// launcher — R14 ladder + optimized head (prep hoist, embsplit halved,
// embsplit-b on the side stream)
// =====================================================================
extern "C" void kernel_launch(void* const* d_in, const int* in_sizes, int n_in,
                              void* d_out, int out_size)
{
    (void)in_sizes; (void)n_in; (void)out_size;
    const float* mem = (const float*)d_in[0];
    const float* srl = (const float*)d_in[1];
    const float* emb = (const float*)d_in[2];
    const float* W1  = (const float*)d_in[4];
    const float* b1  = (const float*)d_in[5];
    const float* W2  = (const float*)d_in[6];
    const float* b2  = (const float*)d_in[7];
    const float* mat = (const float*)d_in[8];
    const float* Wp  = (const float*)d_in[9];
    const float* bp  = (const float*)d_in[10];
    float* outp = (float*)d_out;

#define SYM(v, s) cudaGetSymbolAddress((void**)&v, s)
    bf16 *embh, *embl, *memh, *meml, *srlh, *srll;
    bf16 *hh, *hl, *qh, *ql, *yh, *yl, *ath, *atl;
    bf16 *w1th, *w1tl, *w2th, *w2tl, *math_, *matl, *wph, *wpl;
    float *b1p, *b2p;
    SYM(embh, g_embh); SYM(embl, g_embl);
    SYM(memh, g_memh); SYM(meml, g_meml);
    SYM(srlh, g_srlh); SYM(srll, g_srll);
    SYM(hh, g_hh); SYM(hl, g_hl);
    SYM(qh, g_qh); SYM(ql, g_ql);
    SYM(yh, g_yh); SYM(yl, g_yl);
    SYM(ath, g_ath); SYM(atl, g_atl);
    SYM(w1th, g_w1th); SYM(w1tl, g_w1tl);
    SYM(w2th, g_w2th); SYM(w2tl, g_w2tl);
    SYM(math_, g_math); SYM(matl, g_matl);
    SYM(wph, g_wph); SYM(wpl, g_wpl);
    SYM(b1p, g_b1p); SYM(b2p, g_b2p);
#undef SYM

    static cudaStream_t s2 = nullptr;
    static cudaEvent_t evF = nullptr, evEb = nullptr, evQa = nullptr,
                       evQb = nullptr, evAa = nullptr, evAb = nullptr;
    if (s2 == nullptr) {
        cudaStreamCreateWithFlags(&s2, cudaStreamNonBlocking);
        cudaEventCreateWithFlags(&evF, cudaEventDisableTiming);
        cudaEventCreateWithFlags(&evEb, cudaEventDisableTiming);
        cudaEventCreateWithFlags(&evQa, cudaEventDisableTiming);
        cudaEventCreateWithFlags(&evQb, cudaEventDisableTiming);
        cudaEventCreateWithFlags(&evAa, cudaEventDisableTiming);
        cudaEventCreateWithFlags(&evAb, cudaEventDisableTiming);
        cudaFuncSetAttribute(attn_kernel,
                             cudaFuncAttributeMaxDynamicSharedMemorySize, ATTN_SMEM_BYTES);
        cudaFuncSetAttribute(gemm_bf16<5, true, true>,
                             cudaFuncAttributeMaxDynamicSharedMemorySize, GEMM_SMEM_B(5));
        cudaFuncSetAttribute(gemm_bf16<4, true, true>,
                             cudaFuncAttributeMaxDynamicSharedMemorySize, GEMM_SMEM_B(4));
        cudaFuncSetAttribute(gemm_bf16<4, false, true>,
                             cudaFuncAttributeMaxDynamicSharedMemorySize, GEMM_SMEM_B(4));
        cudaFuncSetAttribute(gemm_bf16<4, false, false>,
                             cudaFuncAttributeMaxDynamicSharedMemorySize, GEMM_SMEM_B(4));
    }

    // fork
    cudaEventRecord(evF, 0);
    cudaStreamWaitEvent(s2, evF, 0);

    // ---- s2: small preps, embsplit-b (evEb), G3a, G3b ----
    {
        long long n2 = (long long)MTOT * MEMP / 2;
        split_pad2<<<(unsigned)((n2 + 255) / 256), 256, 0, s2>>>(mem, memh, meml, n2, DDIM, MEMP);
        tsplit<<<(MATNP * MEMP + 255) / 256, 256, 0, s2>>>(mat, math_, matl, DDIM, DDIM, MEMP, MATNP);
        n2 = (long long)MTOT * VDIM / 2;
        split_pad2<<<(unsigned)((n2 + 255) / 256), 256, 0, s2>>>(srl, srlh, srll, n2, VDIM, VDIM);
        n2 = (long long)VDIM * VDIM / 2;
        split_pad2<<<(unsigned)((n2 + 255) / 256), 256, 0, s2>>>(Wp, wph, wpl, n2, VDIM, VDIM);
        long long n2h = (long long)HM * EMB / 2;
        split_pad2<<<(unsigned)((n2h + 255) / 256), 256, 0, s2>>>(
            emb + (size_t)HM * EMB, embh + (size_t)HM * EMB, embl + (size_t)HM * EMB,
            n2h, EMB, EMB);
        cudaEventRecord(evEb, s2);
        // G3a / G3b
        gemm_bf16<4, false, true><<<dim3(2, 128), 256, GEMM_SMEM_B(4), s2>>>(
            memh, meml, math_, matl, nullptr, nullptr, yh, yl, QP, MEMP);
        gemm_bf16<4, false, true><<<dim3(2, 128), 256, GEMM_SMEM_B(4), s2>>>(
            memh + (size_t)HM * MEMP, meml + (size_t)HM * MEMP, math_, matl,
            nullptr, nullptr, yh + (size_t)HM * QP, yl + (size_t)HM * QP, QP, MEMP);
    }

    // ---- s0: prep_w12, embsplit-a, G1a, G2a (evQa), G1b, G2b (evQb) ----
    {
        prep_w12<<<(WP_D + 255) / 256, 256>>>(W1, W2, b1, b2,
                                              w1th, w1tl, w2th, w2tl, b1p, b2p);
        long long n2h = (long long)HM * EMB / 2;
        split_pad2<<<(unsigned)((n2h + 255) / 256), 256>>>(emb, embh, embl, n2h, EMB, EMB);
        // G1a
        gemm_bf16<5, true, true><<<dim3(2, 128), 256, GEMM_SMEM_B(5)>>>(
            embh, embl, w1th, w1tl, b1p, nullptr, hh, hl, HP, EMB);
        // G2a
        gemm_bf16<4, true, true><<<dim3(2, 128), 256, GEMM_SMEM_B(4)>>>(
            hh, hl, w2th, w2tl, b2p, nullptr, qh, ql, QP, HP);
        cudaEventRecord(evQa, 0);
        // G1b (needs embsplit-b from s2)
        cudaStreamWaitEvent(0, evEb, 0);
        gemm_bf16<5, true, true><<<dim3(2, 128), 256, GEMM_SMEM_B(5)>>>(
            embh + (size_t)HM * EMB, embl + (size_t)HM * EMB, w1th, w1tl, b1p,
            nullptr, hh + (size_t)HM * HP, hl + (size_t)HM * HP, HP, EMB);
        // G2b
        gemm_bf16<4, true, true><<<dim3(2, 128), 256, GEMM_SMEM_B(4)>>>(
            hh + (size_t)HM * HP, hl + (size_t)HM * HP, w2th, w2tl, b2p,
            nullptr, qh + (size_t)HM * QP, ql + (size_t)HM * QP, QP, HP);
        cudaEventRecord(evQb, 0);
    }

    // ---- s2: attnA (after G2a), attnB (after G2b) — both on s2 (R14) ----
    {
        cudaStreamWaitEvent(s2, evQa, 0);
        attn_kernel<<<dim3(SEQ / 128, HB), 256, ATTN_SMEM_BYTES, s2>>>(
            qh, ql, yh, yl, srlh, srll, ath, atl);
        cudaEventRecord(evAa, s2);
        cudaStreamWaitEvent(s2, evQb, 0);
        attn_kernel<<<dim3(SEQ / 128, HB), 256, ATTN_SMEM_BYTES, s2>>>(
            qh + (size_t)HM * QP,   ql + (size_t)HM * QP,
            yh + (size_t)HM * QP,   yl + (size_t)HM * QP,
            srlh + (size_t)HM * VDIM, srll + (size_t)HM * VDIM,
            ath + (size_t)HM * VDIM,  atl + (size_t)HM * VDIM);
        cudaEventRecord(evAb, s2);
    }

    // ---- s0: G5a (after attnA), G5b (after attnB) ----
    cudaStreamWaitEvent(0, evAa, 0);
    gemm_bf16<4, false, false><<<dim3(1, 128), 256, GEMM_SMEM_B(4)>>>(
        ath, atl, wph, wpl, bp, outp, nullptr, nullptr, VDIM, VDIM);
    cudaStreamWaitEvent(0, evAb, 0);
    gemm_bf16<4, false, false><<<dim3(1, 128), 256, GEMM_SMEM_B(4)>>>(
        ath + (size_t)HM * VDIM, atl + (size_t)HM * VDIM, wph, wpl, bp,
        outp + (size_t)HM * VDIM, nullptr, nullptr, VDIM, VDIM);
}